// round 1
// baseline (speedup 1.0000x reference)
#include <cuda_runtime.h>

#define Nn 100000
#define Ee 1600000
#define Dd 64
#define Gg 256

// ---- device scratch (no allocations allowed) ----
__device__ float g_xa[Nn * Dd];      // ping  (holds dinv-scaled features)
__device__ float g_xb[Nn * Dd];      // pong
__device__ int   g_deg[Nn];
__device__ int   g_rowstart[Nn];
__device__ int   g_cursor[Nn];
__device__ float g_dinv[Nn];
__device__ int   g_col[Ee];          // CSR (grouped by dst, stores src)
__device__ float g_h[Gg * 2 * Dd];   // pooled [mean | max]
__device__ int   g_counter;

// ---------------- CSR build ----------------
__global__ void k_init() {
    int i = blockIdx.x * blockDim.x + threadIdx.x;
    if (i < Nn) g_deg[i] = 0;
    if (i == 0) g_counter = 0;
}

__global__ void k_hist(const int* __restrict__ dst) {
    int e = blockIdx.x * blockDim.x + threadIdx.x;
    if (e < Ee) atomicAdd(&g_deg[dst[e]], 1);
}

__global__ void k_alloc() {
    int i = blockIdx.x * blockDim.x + threadIdx.x;
    if (i < Nn) {
        int d = g_deg[i];
        int rs = atomicAdd(&g_counter, d);
        g_rowstart[i] = rs;
        g_cursor[i]   = rs;
        g_dinv[i]     = rsqrtf((float)(d + 1));   // +1 = self loop
    }
}

__global__ void k_scatter(const int* __restrict__ src, const int* __restrict__ dst) {
    int e = blockIdx.x * blockDim.x + threadIdx.x;
    if (e < Ee) {
        int p = atomicAdd(&g_cursor[dst[e]], 1);
        g_col[p] = src[e];
    }
}

// ---------------- embedding gather (writes dinv-scaled x0) ----------------
__global__ void k_embed(const int* __restrict__ tok, const float* __restrict__ emb) {
    int t = blockIdx.x * blockDim.x + threadIdx.x;  // Nn*16 float4s
    if (t < Nn * 16) {
        int i = t >> 4;
        float4 v = ((const float4*)emb)[tok[i] * 16 + (t & 15)];
        float di = g_dinv[i];
        v.x *= di; v.y *= di; v.z *= di; v.w *= di;
        ((float4*)g_xa)[t] = v;
    }
}

// ---------------- fused layer: aggregate -> GEMM(64x64) -> bias -> relu ----------------
// in_sel: 0 reads g_xa, 1 reads g_xb; output goes to the other buffer.
// scale_out: multiply output by dinv (preparing next layer's input).
__global__ void __launch_bounds__(256) k_layer(int in_sel,
                                               const float* __restrict__ W,
                                               const float* __restrict__ b,
                                               int scale_out) {
    __shared__ float  Ws[Dd * Dd];
    __shared__ float  bs[Dd];
    __shared__ float2 zs[8][32];

    const float* __restrict__ xin = in_sel ? g_xb : g_xa;
    float* __restrict__       xout = in_sel ? g_xa : g_xb;

    for (int i = threadIdx.x; i < Dd * Dd / 4; i += blockDim.x)
        ((float4*)Ws)[i] = ((const float4*)W)[i];
    if (threadIdx.x < Dd / 4)
        ((float4*)bs)[threadIdx.x] = ((const float4*)b)[threadIdx.x];
    __syncthreads();

    int warp = threadIdx.x >> 5, lane = threadIdx.x & 31;
    int gw = blockIdx.x * 8 + warp;
    int stride = gridDim.x * 8;
    const float2* __restrict__ xin2 = (const float2*)xin;

    for (int i = gw; i < Nn; i += stride) {
        // self-loop term (xd[i]) + sum over incoming edges of xd[src]
        float2 acc = xin2[i * 32 + lane];
        int rs  = g_rowstart[i];
        int cnt = g_deg[i];
        int e = 0;
        for (; e + 4 <= cnt; e += 4) {
            int s0 = g_col[rs + e];
            int s1 = g_col[rs + e + 1];
            int s2 = g_col[rs + e + 2];
            int s3 = g_col[rs + e + 3];
            float2 v0 = xin2[s0 * 32 + lane];
            float2 v1 = xin2[s1 * 32 + lane];
            float2 v2 = xin2[s2 * 32 + lane];
            float2 v3 = xin2[s3 * 32 + lane];
            acc.x += (v0.x + v1.x) + (v2.x + v3.x);
            acc.y += (v0.y + v1.y) + (v2.y + v3.y);
        }
        for (; e < cnt; e++) {
            int s = g_col[rs + e];
            float2 v = xin2[s * 32 + lane];
            acc.x += v.x; acc.y += v.y;
        }
        float di = g_dinv[i];
        acc.x *= di; acc.y *= di;        // z = A x  (row i)

        // stage z row in shared, then per-node GEMM z @ W
        __syncwarp();
        zs[warp][lane] = acc;
        __syncwarp();
        const float* z = (const float*)zs[warp];

        float2 o = make_float2(bs[2 * lane], bs[2 * lane + 1]);
#pragma unroll
        for (int k = 0; k < Dd; k++) {
            float zk = z[k];
            float2 w = *(const float2*)&Ws[k * Dd + 2 * lane];
            o.x = fmaf(zk, w.x, o.x);
            o.y = fmaf(zk, w.y, o.y);
        }
        o.x = fmaxf(o.x, 0.f);
        o.y = fmaxf(o.y, 0.f);
        if (scale_out) { o.x *= di; o.y *= di; }
        ((float2*)xout)[i * 32 + lane] = o;
    }
}

// ---------------- graph pooling (mean + max), batch is sorted ----------------
__global__ void __launch_bounds__(128) k_pool(const int* __restrict__ batch) {
    int g = blockIdx.x;
    // [start, end) = nodes belonging to graph g
    int lo = 0, hi = Nn;
    while (lo < hi) { int m = (lo + hi) >> 1; if (batch[m] < g) lo = m + 1; else hi = m; }
    int start = lo;
    hi = Nn;
    while (lo < hi) { int m = (lo + hi) >> 1; if (batch[m] < g + 1) lo = m + 1; else hi = m; }
    int end = lo;

    int warp = threadIdx.x >> 5, lane = threadIdx.x & 31;
    const float2* __restrict__ x2 = (const float2*)g_xb;  // final layer output (unscaled)
    float2 s  = make_float2(0.f, 0.f);
    float2 mx = make_float2(0.f, 0.f);   // relu output >= 0, so 0 matches ref's empty->0
    for (int i = start + warp; i < end; i += 4) {
        float2 v = x2[i * 32 + lane];
        s.x += v.x; s.y += v.y;
        mx.x = fmaxf(mx.x, v.x); mx.y = fmaxf(mx.y, v.y);
    }
    __shared__ float2 ss[4][32], sm[4][32];
    ss[warp][lane] = s; sm[warp][lane] = mx;
    __syncthreads();
    if (warp == 0) {
        for (int w = 1; w < 4; w++) {
            s.x += ss[w][lane].x; s.y += ss[w][lane].y;
            mx.x = fmaxf(mx.x, sm[w][lane].x); mx.y = fmaxf(mx.y, sm[w][lane].y);
        }
        float inv = 1.f / fmaxf((float)(end - start), 1.f);
        g_h[g * 128 + 2 * lane]          = s.x * inv;
        g_h[g * 128 + 2 * lane + 1]      = s.y * inv;
        g_h[g * 128 + 64 + 2 * lane]     = mx.x;
        g_h[g * 128 + 64 + 2 * lane + 1] = mx.y;
    }
}

// ---------------- classifier head ----------------
__global__ void __launch_bounds__(64) k_cls(const float* __restrict__ Wc1,
                                            const float* __restrict__ bc1,
                                            const float* __restrict__ Wc2,
                                            const float* __restrict__ bc2,
                                            float* __restrict__ out) {
    int g = blockIdx.x, j = threadIdx.x;
    __shared__ float hs[128], hid[64];
    hs[j]      = g_h[g * 128 + j];
    hs[j + 64] = g_h[g * 128 + j + 64];
    __syncthreads();
    float acc = bc1[j];
#pragma unroll
    for (int k = 0; k < 128; k++)
        acc = fmaf(hs[k], Wc1[k * 64 + j], acc);
    hid[j] = fmaxf(acc, 0.f);
    __syncthreads();
    if (j < 2) {
        float a = bc2[j];
#pragma unroll
        for (int k = 0; k < 64; k++)
            a = fmaf(hid[k], Wc2[k * 2 + j], a);
        out[g * 2 + j] = a;
    }
}

extern "C" void kernel_launch(void* const* d_in, const int* in_sizes, int n_in,
                              void* d_out, int out_size) {
    const int*   tok   = (const int*)d_in[0];
    const int*   ei    = (const int*)d_in[1];   // (2, E) row-major
    const int*   batch = (const int*)d_in[2];
    const float* emb   = (const float*)d_in[3];
    const float* W0 = (const float*)d_in[4];  const float* b0 = (const float*)d_in[5];
    const float* W1 = (const float*)d_in[6];  const float* b1 = (const float*)d_in[7];
    const float* W2 = (const float*)d_in[8];  const float* b2 = (const float*)d_in[9];
    const float* Wc1 = (const float*)d_in[10]; const float* bc1 = (const float*)d_in[11];
    const float* Wc2 = (const float*)d_in[12]; const float* bc2 = (const float*)d_in[13];
    float* out = (float*)d_out;

    const int* src = ei;
    const int* dst = ei + Ee;

    k_init   <<<(Nn + 255) / 256, 256>>>();
    k_hist   <<<(Ee + 255) / 256, 256>>>(dst);
    k_alloc  <<<(Nn + 255) / 256, 256>>>();
    k_scatter<<<(Ee + 255) / 256, 256>>>(src, dst);
    k_embed  <<<(Nn * 16 + 255) / 256, 256>>>(tok, emb);

    const int LGRID = 1480;                        // 8 warps/block, grid-stride over nodes
    k_layer<<<LGRID, 256>>>(0, W0, b0, 1);         // xa -> xb (scaled)
    k_layer<<<LGRID, 256>>>(1, W1, b1, 1);         // xb -> xa (scaled)
    k_layer<<<LGRID, 256>>>(0, W2, b2, 0);         // xa -> xb (unscaled, for pooling)

    k_pool<<<Gg, 128>>>(batch);
    k_cls <<<Gg, 64>>>(Wc1, bc1, Wc2, bc2, out);
}

// round 2
// speedup vs baseline: 1.0531x; 1.0531x over previous
#include <cuda_runtime.h>
#include <cuda_fp16.h>

#define Nn 100000
#define Ee 1600000
#define Dd 64
#define Gg 256
#define SCALE 256.0f
#define INV_SCALE (1.0f / 256.0f)

// ---- device scratch (no allocations allowed) ----
__device__ __half g_ha[Nn * Dd];     // ping  (fp16, holds dinv*SCALE-scaled features)
__device__ __half g_hb[Nn * Dd];     // pong
__device__ float  g_xf[Nn * Dd];     // final-layer fp32 output (for exact pooling)
__device__ int    g_deg[Nn];
__device__ int    g_rowstart[Nn];
__device__ int    g_cursor[Nn];
__device__ float  g_dinv[Nn];
__device__ int    g_col[Ee];         // CSR (grouped by dst, stores src)
__device__ float  g_h[Gg * 2 * Dd];  // pooled [mean | max]
__device__ int    g_counter;

// ---------------- CSR build ----------------
__global__ void k_init() {
    int i = blockIdx.x * blockDim.x + threadIdx.x;
    if (i < Nn) g_deg[i] = 0;
    if (i == 0) g_counter = 0;
}

__global__ void k_hist(const int4* __restrict__ dst4) {
    int e = blockIdx.x * blockDim.x + threadIdx.x;   // Ee/4 threads
    if (e < Ee / 4) {
        int4 d = dst4[e];
        atomicAdd(&g_deg[d.x], 1);
        atomicAdd(&g_deg[d.y], 1);
        atomicAdd(&g_deg[d.z], 1);
        atomicAdd(&g_deg[d.w], 1);
    }
}

__global__ void k_alloc() {
    int i = blockIdx.x * blockDim.x + threadIdx.x;
    if (i < Nn) {
        int d = g_deg[i];
        int rs = atomicAdd(&g_counter, d);
        g_rowstart[i] = rs;
        g_cursor[i]   = rs;
        g_dinv[i]     = rsqrtf((float)(d + 1));   // +1 = self loop
    }
}

__global__ void k_scatter(const int4* __restrict__ src4, const int4* __restrict__ dst4) {
    int e = blockIdx.x * blockDim.x + threadIdx.x;   // Ee/4 threads
    if (e < Ee / 4) {
        int4 s = src4[e];
        int4 d = dst4[e];
        g_col[atomicAdd(&g_cursor[d.x], 1)] = s.x;
        g_col[atomicAdd(&g_cursor[d.y], 1)] = s.y;
        g_col[atomicAdd(&g_cursor[d.z], 1)] = s.z;
        g_col[atomicAdd(&g_cursor[d.w], 1)] = s.w;
    }
}

// ---------------- embedding gather (writes dinv*SCALE-scaled fp16 x0) ----------------
__global__ void k_embed(const int* __restrict__ tok, const float* __restrict__ emb) {
    int t = blockIdx.x * blockDim.x + threadIdx.x;  // Nn*16 (4 floats each)
    if (t < Nn * 16) {
        int i = t >> 4;
        float4 v = ((const float4*)emb)[tok[i] * 16 + (t & 15)];
        float s = g_dinv[i] * SCALE;
        __half2 h0 = __floats2half2_rn(v.x * s, v.y * s);
        __half2 h1 = __floats2half2_rn(v.z * s, v.w * s);
        ((__half2*)g_ha)[2 * t]     = h0;
        ((__half2*)g_ha)[2 * t + 1] = h1;
    }
}

// ---------------- fused layer: aggregate(fp16) -> GEMM(64x64 fp32) -> bias -> relu ----------------
// in_sel: 0 reads g_ha, 1 reads g_hb. out_mode: 0 -> fp16 to the other half buffer
// (scaled by dinv*SCALE for the next layer), 1 -> fp32 to g_xf (unscaled, final layer).
__global__ void __launch_bounds__(256) k_layer(int in_sel,
                                               const float* __restrict__ W,
                                               const float* __restrict__ b,
                                               int out_mode) {
    __shared__ float  Ws[Dd * Dd];
    __shared__ float  bs[Dd];
    __shared__ float2 zs[8][32];

    const __half2* __restrict__ xin2 = (const __half2*)(in_sel ? g_hb : g_ha);
    __half2* __restrict__ xoh = (__half2*)(in_sel ? g_ha : g_hb);

    for (int i = threadIdx.x; i < Dd * Dd / 4; i += blockDim.x)
        ((float4*)Ws)[i] = ((const float4*)W)[i];
    if (threadIdx.x < Dd / 4)
        ((float4*)bs)[threadIdx.x] = ((const float4*)b)[threadIdx.x];
    __syncthreads();

    int warp = threadIdx.x >> 5, lane = threadIdx.x & 31;
    int gw = blockIdx.x * 8 + warp;
    int stride = gridDim.x * 8;

    for (int i = gw; i < Nn; i += stride) {
        // self-loop term + sum over incoming edges (all values pre-scaled by dinv*SCALE)
        float2 acc = __half22float2(xin2[i * 32 + lane]);
        int rs  = g_rowstart[i];
        int cnt = g_deg[i];
        int e = 0;
        for (; e + 8 <= cnt; e += 8) {
            int s0 = g_col[rs + e];
            int s1 = g_col[rs + e + 1];
            int s2 = g_col[rs + e + 2];
            int s3 = g_col[rs + e + 3];
            int s4 = g_col[rs + e + 4];
            int s5 = g_col[rs + e + 5];
            int s6 = g_col[rs + e + 6];
            int s7 = g_col[rs + e + 7];
            float2 v0 = __half22float2(xin2[s0 * 32 + lane]);
            float2 v1 = __half22float2(xin2[s1 * 32 + lane]);
            float2 v2 = __half22float2(xin2[s2 * 32 + lane]);
            float2 v3 = __half22float2(xin2[s3 * 32 + lane]);
            float2 v4 = __half22float2(xin2[s4 * 32 + lane]);
            float2 v5 = __half22float2(xin2[s5 * 32 + lane]);
            float2 v6 = __half22float2(xin2[s6 * 32 + lane]);
            float2 v7 = __half22float2(xin2[s7 * 32 + lane]);
            acc.x += ((v0.x + v1.x) + (v2.x + v3.x)) + ((v4.x + v5.x) + (v6.x + v7.x));
            acc.y += ((v0.y + v1.y) + (v2.y + v3.y)) + ((v4.y + v5.y) + (v6.y + v7.y));
        }
        for (; e < cnt; e++) {
            int s = g_col[rs + e];
            float2 v = __half22float2(xin2[s * 32 + lane]);
            acc.x += v.x; acc.y += v.y;
        }
        float di = g_dinv[i];
        float f = di * INV_SCALE;        // undo storage scale, apply dst-side dinv
        acc.x *= f; acc.y *= f;          // z = (A x)_i

        // stage z row in shared, then per-node GEMM z @ W
        __syncwarp();
        zs[warp][lane] = acc;
        __syncwarp();
        const float* z = (const float*)zs[warp];

        float2 o = make_float2(bs[2 * lane], bs[2 * lane + 1]);
#pragma unroll
        for (int k = 0; k < Dd; k++) {
            float zk = z[k];
            float2 w = *(const float2*)&Ws[k * Dd + 2 * lane];
            o.x = fmaf(zk, w.x, o.x);
            o.y = fmaf(zk, w.y, o.y);
        }
        o.x = fmaxf(o.x, 0.f);
        o.y = fmaxf(o.y, 0.f);
        if (out_mode == 0) {
            float so = di * SCALE;       // pre-scale for next layer's gather
            xoh[i * 32 + lane] = __floats2half2_rn(o.x * so, o.y * so);
        } else {
            ((float2*)g_xf)[i * 32 + lane] = o;
        }
    }
}

// ---------------- graph pooling (mean + max), batch is sorted ----------------
__global__ void __launch_bounds__(128) k_pool(const int* __restrict__ batch) {
    int g = blockIdx.x;
    int lo = 0, hi = Nn;
    while (lo < hi) { int m = (lo + hi) >> 1; if (batch[m] < g) lo = m + 1; else hi = m; }
    int start = lo;
    hi = Nn;
    while (lo < hi) { int m = (lo + hi) >> 1; if (batch[m] < g + 1) lo = m + 1; else hi = m; }
    int end = lo;

    int warp = threadIdx.x >> 5, lane = threadIdx.x & 31;
    const float2* __restrict__ x2 = (const float2*)g_xf;
    float2 s  = make_float2(0.f, 0.f);
    float2 mx = make_float2(0.f, 0.f);   // relu output >= 0, matches ref's empty->0
    for (int i = start + warp; i < end; i += 4) {
        float2 v = x2[i * 32 + lane];
        s.x += v.x; s.y += v.y;
        mx.x = fmaxf(mx.x, v.x); mx.y = fmaxf(mx.y, v.y);
    }
    __shared__ float2 ss[4][32], sm[4][32];
    ss[warp][lane] = s; sm[warp][lane] = mx;
    __syncthreads();
    if (warp == 0) {
        for (int w = 1; w < 4; w++) {
            s.x += ss[w][lane].x; s.y += ss[w][lane].y;
            mx.x = fmaxf(mx.x, sm[w][lane].x); mx.y = fmaxf(mx.y, sm[w][lane].y);
        }
        float inv = 1.f / fmaxf((float)(end - start), 1.f);
        g_h[g * 128 + 2 * lane]          = s.x * inv;
        g_h[g * 128 + 2 * lane + 1]      = s.y * inv;
        g_h[g * 128 + 64 + 2 * lane]     = mx.x;
        g_h[g * 128 + 64 + 2 * lane + 1] = mx.y;
    }
}

// ---------------- classifier head ----------------
__global__ void __launch_bounds__(64) k_cls(const float* __restrict__ Wc1,
                                            const float* __restrict__ bc1,
                                            const float* __restrict__ Wc2,
                                            const float* __restrict__ bc2,
                                            float* __restrict__ out) {
    int g = blockIdx.x, j = threadIdx.x;
    __shared__ float hs[128], hid[64];
    hs[j]      = g_h[g * 128 + j];
    hs[j + 64] = g_h[g * 128 + j + 64];
    __syncthreads();
    float acc = bc1[j];
#pragma unroll
    for (int k = 0; k < 128; k++)
        acc = fmaf(hs[k], Wc1[k * 64 + j], acc);
    hid[j] = fmaxf(acc, 0.f);
    __syncthreads();
    if (j < 2) {
        float a = bc2[j];
#pragma unroll
        for (int k = 0; k < 64; k++)
            a = fmaf(hid[k], Wc2[k * 2 + j], a);
        out[g * 2 + j] = a;
    }
}

extern "C" void kernel_launch(void* const* d_in, const int* in_sizes, int n_in,
                              void* d_out, int out_size) {
    const int*   tok   = (const int*)d_in[0];
    const int*   ei    = (const int*)d_in[1];   // (2, E) row-major
    const int*   batch = (const int*)d_in[2];
    const float* emb   = (const float*)d_in[3];
    const float* W0 = (const float*)d_in[4];  const float* b0 = (const float*)d_in[5];
    const float* W1 = (const float*)d_in[6];  const float* b1 = (const float*)d_in[7];
    const float* W2 = (const float*)d_in[8];  const float* b2 = (const float*)d_in[9];
    const float* Wc1 = (const float*)d_in[10]; const float* bc1 = (const float*)d_in[11];
    const float* Wc2 = (const float*)d_in[12]; const float* bc2 = (const float*)d_in[13];
    float* out = (float*)d_out;

    const int4* src4 = (const int4*)ei;
    const int4* dst4 = (const int4*)(ei + Ee);

    k_init   <<<(Nn + 255) / 256, 256>>>();
    k_hist   <<<(Ee / 4 + 255) / 256, 256>>>(dst4);
    k_alloc  <<<(Nn + 255) / 256, 256>>>();
    k_scatter<<<(Ee / 4 + 255) / 256, 256>>>(src4, dst4);
    k_embed  <<<(Nn * 16 + 255) / 256, 256>>>(tok, emb);

    const int LGRID = 1480;                        // 8 warps/block, grid-stride over nodes
    k_layer<<<LGRID, 256>>>(0, W0, b0, 0);         // ha -> hb (fp16, scaled)
    k_layer<<<LGRID, 256>>>(1, W1, b1, 0);         // hb -> ha (fp16, scaled)
    k_layer<<<LGRID, 256>>>(0, W2, b2, 1);         // ha -> g_xf (fp32, unscaled)

    k_pool<<<Gg, 128>>>(batch);
    k_cls <<<Gg, 64>>>(Wc1, bc1, Wc2, bc2, out);
}

// round 3
// speedup vs baseline: 1.0833x; 1.0287x over previous
#include <cuda_runtime.h>
#include <cuda_fp16.h>

#define Nn 100000
#define Ee 1600000
#define Dd 64
#define Gg 256
#define SCALE 256.0f
#define INV_SCALE (1.0f / 256.0f)

// ---- device scratch (no allocations allowed) ----
__device__ __half g_ha[Nn * Dd];       // ping  (fp16, dinv*SCALE-scaled features)
__device__ __half g_hb[Nn * Dd];       // pong
__device__ float  g_xf[Nn * Dd];       // final-layer fp32 output (exact pooling)
__device__ int    g_deg[Nn];
__device__ int    g_rowstart[Nn];
__device__ int    g_cursor[Nn];
__device__ float  g_dinv[Nn];
__device__ int    g_col[Ee + 64];      // CSR (grouped by dst, stores src); padded for clamp-free overread guard
__device__ float  g_h[Gg * 2 * Dd];    // pooled [mean | max]
__device__ int    g_counter;

// ---------------- CSR build ----------------
__global__ void k_init() {
    int i = blockIdx.x * blockDim.x + threadIdx.x;
    if (i < Nn) g_deg[i] = 0;
    if (i == 0) g_counter = 0;
}

__global__ void k_hist(const int4* __restrict__ dst4) {
    int e = blockIdx.x * blockDim.x + threadIdx.x;   // Ee/4 threads
    if (e < Ee / 4) {
        int4 d = dst4[e];
        atomicAdd(&g_deg[d.x], 1);
        atomicAdd(&g_deg[d.y], 1);
        atomicAdd(&g_deg[d.z], 1);
        atomicAdd(&g_deg[d.w], 1);
    }
}

__global__ void k_alloc() {
    int i = blockIdx.x * blockDim.x + threadIdx.x;
    if (i < Nn) {
        int d = g_deg[i];
        int rs = atomicAdd(&g_counter, d);
        g_rowstart[i] = rs;
        g_cursor[i]   = rs;
        g_dinv[i]     = rsqrtf((float)(d + 1));   // +1 = self loop
    }
}

__global__ void k_scatter(const int4* __restrict__ src4, const int4* __restrict__ dst4) {
    int e = blockIdx.x * blockDim.x + threadIdx.x;   // Ee/4 threads
    if (e < Ee / 4) {
        int4 s = src4[e];
        int4 d = dst4[e];
        g_col[atomicAdd(&g_cursor[d.x], 1)] = s.x;
        g_col[atomicAdd(&g_cursor[d.y], 1)] = s.y;
        g_col[atomicAdd(&g_cursor[d.z], 1)] = s.z;
        g_col[atomicAdd(&g_cursor[d.w], 1)] = s.w;
    }
}

// ---------------- embedding gather (writes dinv*SCALE-scaled fp16 x0) ----------------
__global__ void k_embed(const int* __restrict__ tok, const float* __restrict__ emb) {
    int t = blockIdx.x * blockDim.x + threadIdx.x;  // Nn*16 (4 floats each)
    if (t < Nn * 16) {
        int i = t >> 4;
        float4 v = ((const float4*)emb)[tok[i] * 16 + (t & 15)];
        float s = g_dinv[i] * SCALE;
        __half2 h0 = __floats2half2_rn(v.x * s, v.y * s);
        __half2 h1 = __floats2half2_rn(v.z * s, v.w * s);
        ((__half2*)g_ha)[2 * t]     = h0;
        ((__half2*)g_ha)[2 * t + 1] = h1;
    }
}

// ---------------- fused layer: two nodes per warp (16 lanes each) ----------------
// aggregate(fp16) -> GEMM(64x64 fp32) -> bias -> relu
__device__ __forceinline__ void unpack_add(float4& a, uint2 r) {
    __half2 h0 = *(__half2*)&r.x;
    __half2 h1 = *(__half2*)&r.y;
    float2 f0 = __half22float2(h0);
    float2 f1 = __half22float2(h1);
    a.x += f0.x; a.y += f0.y; a.z += f1.x; a.w += f1.y;
}

__global__ void __launch_bounds__(256) k_layer(int in_sel,
                                               const float* __restrict__ W,
                                               const float* __restrict__ b,
                                               int out_mode) {
    __shared__ float Ws[Dd * Dd];
    __shared__ float bs[Dd];
    __shared__ float zs[8][2][68];   // per warp, per half-warp; padded rows (bank-safe)

    const uint2* __restrict__ xin2 = (const uint2*)(in_sel ? g_hb : g_ha);
    uint2* __restrict__ xoh = (uint2*)(in_sel ? g_ha : g_hb);

    for (int i = threadIdx.x; i < Dd * Dd / 4; i += blockDim.x)
        ((float4*)Ws)[i] = ((const float4*)W)[i];
    if (threadIdx.x < Dd / 4)
        ((float4*)bs)[threadIdx.x] = ((const float4*)b)[threadIdx.x];
    __syncthreads();

    int warp = threadIdx.x >> 5, lane = threadIdx.x & 31;
    int hw = lane >> 4;          // which half-warp (node within pair)
    int sl = lane & 15;          // sub-lane: owns 4 consecutive feature cols
    int gw = blockIdx.x * 8 + warp;
    int TW = gridDim.x * 8;

    for (int p = gw; 2 * p < Nn; p += TW) {
        int i = 2 * p + hw;                 // this half-warp's node (Nn is even)

        // self-loop term (pre-scaled by dinv*SCALE)
        float4 acc = make_float4(0.f, 0.f, 0.f, 0.f);
        unpack_add(acc, xin2[i * 16 + sl]);

        int rs  = g_rowstart[i];
        int cnt = g_deg[i];
        int cmax = max(cnt, __shfl_xor_sync(0xffffffffu, cnt, 16));

        for (int e = 0; e < cmax; e += 4) {
            int i0 = min(rs + e,     Ee - 1);
            int i1 = min(rs + e + 1, Ee - 1);
            int i2 = min(rs + e + 2, Ee - 1);
            int i3 = min(rs + e + 3, Ee - 1);
            int s0 = g_col[i0];
            int s1 = g_col[i1];
            int s2 = g_col[i2];
            int s3 = g_col[i3];
            uint2 r0 = xin2[s0 * 16 + sl];
            uint2 r1 = xin2[s1 * 16 + sl];
            uint2 r2 = xin2[s2 * 16 + sl];
            uint2 r3 = xin2[s3 * 16 + sl];
            if (e     < cnt) unpack_add(acc, r0);
            if (e + 1 < cnt) unpack_add(acc, r1);
            if (e + 2 < cnt) unpack_add(acc, r2);
            if (e + 3 < cnt) unpack_add(acc, r3);
        }

        float di = g_dinv[i];
        float f = di * INV_SCALE;           // undo storage scale + dst-side dinv
        acc.x *= f; acc.y *= f; acc.z *= f; acc.w *= f;

        // stage z row in shared, then GEMM z @ W (each lane -> 4 output cols)
        __syncwarp();
        float* zr = zs[warp][hw];
        zr[4 * sl + 0] = acc.x;
        zr[4 * sl + 1] = acc.y;
        zr[4 * sl + 2] = acc.z;
        zr[4 * sl + 3] = acc.w;
        __syncwarp();

        float4 o = ((const float4*)bs)[sl];
#pragma unroll
        for (int k = 0; k < Dd; k++) {
            float zk = zr[k];
            float4 w = ((const float4*)(Ws + k * Dd))[sl];
            o.x = fmaf(zk, w.x, o.x);
            o.y = fmaf(zk, w.y, o.y);
            o.z = fmaf(zk, w.z, o.z);
            o.w = fmaf(zk, w.w, o.w);
        }
        o.x = fmaxf(o.x, 0.f); o.y = fmaxf(o.y, 0.f);
        o.z = fmaxf(o.z, 0.f); o.w = fmaxf(o.w, 0.f);

        if (out_mode == 0) {
            float so = di * SCALE;          // pre-scale for next layer's gather
            __half2 h0 = __floats2half2_rn(o.x * so, o.y * so);
            __half2 h1 = __floats2half2_rn(o.z * so, o.w * so);
            uint2 r;
            r.x = *(unsigned*)&h0;
            r.y = *(unsigned*)&h1;
            xoh[i * 16 + sl] = r;
        } else {
            ((float4*)g_xf)[i * 16 + sl] = o;
        }
    }
}

// ---------------- graph pooling (mean + max), batch is sorted ----------------
__global__ void __launch_bounds__(128) k_pool(const int* __restrict__ batch) {
    int g = blockIdx.x;
    int lo = 0, hi = Nn;
    while (lo < hi) { int m = (lo + hi) >> 1; if (batch[m] < g) lo = m + 1; else hi = m; }
    int start = lo;
    hi = Nn;
    while (lo < hi) { int m = (lo + hi) >> 1; if (batch[m] < g + 1) lo = m + 1; else hi = m; }
    int end = lo;

    int warp = threadIdx.x >> 5, lane = threadIdx.x & 31;
    const float2* __restrict__ x2 = (const float2*)g_xf;
    float2 s  = make_float2(0.f, 0.f);
    float2 mx = make_float2(0.f, 0.f);   // relu output >= 0, matches ref's empty->0
    for (int i = start + warp; i < end; i += 4) {
        float2 v = x2[i * 32 + lane];
        s.x += v.x; s.y += v.y;
        mx.x = fmaxf(mx.x, v.x); mx.y = fmaxf(mx.y, v.y);
    }
    __shared__ float2 ss[4][32], sm[4][32];
    ss[warp][lane] = s; sm[warp][lane] = mx;
    __syncthreads();
    if (warp == 0) {
        for (int w = 1; w < 4; w++) {
            s.x += ss[w][lane].x; s.y += ss[w][lane].y;
            mx.x = fmaxf(mx.x, sm[w][lane].x); mx.y = fmaxf(mx.y, sm[w][lane].y);
        }
        float inv = 1.f / fmaxf((float)(end - start), 1.f);
        g_h[g * 128 + 2 * lane]          = s.x * inv;
        g_h[g * 128 + 2 * lane + 1]      = s.y * inv;
        g_h[g * 128 + 64 + 2 * lane]     = mx.x;
        g_h[g * 128 + 64 + 2 * lane + 1] = mx.y;
    }
}

// ---------------- classifier head ----------------
__global__ void __launch_bounds__(64) k_cls(const float* __restrict__ Wc1,
                                            const float* __restrict__ bc1,
                                            const float* __restrict__ Wc2,
                                            const float* __restrict__ bc2,
                                            float* __restrict__ out) {
    int g = blockIdx.x, j = threadIdx.x;
    __shared__ float hs[128], hid[64];
    hs[j]      = g_h[g * 128 + j];
    hs[j + 64] = g_h[g * 128 + j + 64];
    __syncthreads();
    float acc = bc1[j];
#pragma unroll
    for (int k = 0; k < 128; k++)
        acc = fmaf(hs[k], Wc1[k * 64 + j], acc);
    hid[j] = fmaxf(acc, 0.f);
    __syncthreads();
    if (j < 2) {
        float a = bc2[j];
#pragma unroll
        for (int k = 0; k < 64; k++)
            a = fmaf(hid[k], Wc2[k * 2 + j], a);
        out[g * 2 + j] = a;
    }
}

extern "C" void kernel_launch(void* const* d_in, const int* in_sizes, int n_in,
                              void* d_out, int out_size) {
    const int*   tok   = (const int*)d_in[0];
    const int*   ei    = (const int*)d_in[1];   // (2, E) row-major
    const int*   batch = (const int*)d_in[2];
    const float* emb   = (const float*)d_in[3];
    const float* W0 = (const float*)d_in[4];  const float* b0 = (const float*)d_in[5];
    const float* W1 = (const float*)d_in[6];  const float* b1 = (const float*)d_in[7];
    const float* W2 = (const float*)d_in[8];  const float* b2 = (const float*)d_in[9];
    const float* Wc1 = (const float*)d_in[10]; const float* bc1 = (const float*)d_in[11];
    const float* Wc2 = (const float*)d_in[12]; const float* bc2 = (const float*)d_in[13];
    float* out = (float*)d_out;

    const int4* src4 = (const int4*)ei;
    const int4* dst4 = (const int4*)(ei + Ee);

    k_init   <<<(Nn + 255) / 256, 256>>>();
    k_hist   <<<(Ee / 4 + 255) / 256, 256>>>(dst4);
    k_alloc  <<<(Nn + 255) / 256, 256>>>();
    k_scatter<<<(Ee / 4 + 255) / 256, 256>>>(src4, dst4);
    k_embed  <<<(Nn * 16 + 255) / 256, 256>>>(tok, emb);

    const int LGRID = 888;                         // ~6 blocks/SM resident, grid-stride
    k_layer<<<LGRID, 256>>>(0, W0, b0, 0);         // ha -> hb (fp16, scaled)
    k_layer<<<LGRID, 256>>>(1, W1, b1, 0);         // hb -> ha (fp16, scaled)
    k_layer<<<LGRID, 256>>>(0, W2, b2, 1);         // ha -> g_xf (fp32, unscaled)

    k_pool<<<Gg, 128>>>(batch);
    k_cls <<<Gg, 64>>>(Wc1, bc1, Wc2, bc2, out);
}